// round 13
// baseline (speedup 1.0000x reference)
#include <cuda_runtime.h>
#include <math.h>

#define Bn   8
#define Sn   1024
#define Dm   128
#define Hn   8
#define HD   16
#define FFn  256
#define Lnum 4
#define LWn  128
#define EPSf 1e-5f
#define ROWS (Bn * Sn)   // 8192
#define QB   128               // attention queries per block
#define NKMAX (QB + 2 * LWn)   // 384

typedef unsigned long long u64;

// ---------------- scratch (static device memory; no runtime allocs) ----------------
__device__ float g_x[ROWS * Dm];
__device__ float g_qkv[ROWS * 3 * Dm];
__device__ float g_ctx[ROWS * Dm];

__device__ __forceinline__ float warp_sum(float v) {
#pragma unroll
    for (int o = 16; o > 0; o >>= 1) v += __shfl_xor_sync(0xffffffffu, v, o);
    return v;
}

// ---- packed f32x2 helpers (Blackwell dual-FP32) ----
__device__ __forceinline__ u64 pk2(float x, float y) {
    u64 r;
    asm("mov.b64 %0, {%1, %2};" : "=l"(r) : "f"(x), "f"(y));
    return r;
}
__device__ __forceinline__ void upk2(u64 v, float& x, float& y) {
    asm("mov.b64 {%0, %1}, %2;" : "=f"(x), "=f"(y) : "l"(v));
}
__device__ __forceinline__ void fma2(u64& d, u64 a, u64 b) {
    asm("fma.rn.f32x2 %0, %1, %2, %0;" : "+l"(d) : "l"(a), "l"(b));
}
__device__ __forceinline__ u64 add2(u64 a, u64 b) {
    u64 r;
    asm("add.rn.f32x2 %0, %1, %2;" : "=l"(r) : "l"(a), "l"(b));
    return r;
}
__device__ __forceinline__ float ex2f(float x) {
    float r;
    asm("ex2.approx.f32 %0, %1;" : "=f"(r) : "f"(x));
    return r;
}

// ---------------- embedding + sinusoidal positions ----------------
__global__ void embed_kernel(const int* __restrict__ tok, const float* __restrict__ emb) {
    int idx = blockIdx.x * blockDim.x + threadIdx.x;
    int d  = idx & (Dm - 1);
    int bs = idx >> 7;
    int s  = bs & (Sn - 1);
    int v  = tok[bs];
    int i2 = d & ~1;
    float div = expf(-(float)i2 * (logf(10000.0f) / (float)Dm));
    float arg = (float)s * div;
    float pe  = (d & 1) ? cosf(arg) : sinf(arg);
    g_x[idx] = emb[v * Dm + d] + pe;
}

// ---------------- GEMM 64x64: C = A @ W^T + bias (QKV projection) ----------------
__global__ void __launch_bounds__(128) gemm64x64(
    const float* __restrict__ A, const float* __restrict__ W,
    const float* __restrict__ bias, float* __restrict__ C, int N, int K)
{
    __shared__ float As[2][32][66];
    __shared__ float Bs[2][32][66];

    const int m0 = blockIdx.y * 64, n0 = blockIdx.x * 64;
    const int tid = threadIdx.x;
    const int tx = tid & 15;
    const int ty = tid >> 4;
    const int r8 = tid >> 3;
    const int k4 = tid & 7;

    u64 acc2[4][4];
#pragma unroll
    for (int p = 0; p < 4; p++)
#pragma unroll
        for (int j = 0; j < 4; j++) acc2[p][j] = 0ull;

    float4 apf[4], bpf[4];
#pragma unroll
    for (int i = 0; i < 4; i++) {
        int r = i * 16 + r8;
        apf[i] = *(const float4*)&A[(size_t)(m0 + r) * K + 4 * k4];
        bpf[i] = *(const float4*)&W[(size_t)(n0 + r) * K + 4 * k4];
    }

    int buf = 0;
    for (int kc = 0; kc < K; kc += 32, buf ^= 1) {
#pragma unroll
        for (int i = 0; i < 4; i++) {
            int r = i * 16 + r8;
#pragma unroll
            for (int c = 0; c < 4; c++) {
                As[buf][4 * k4 + c][r] = ((const float*)&apf[i])[c];
                Bs[buf][4 * k4 + c][r] = ((const float*)&bpf[i])[c];
            }
        }
        __syncthreads();

        if (kc + 32 < K) {
#pragma unroll
            for (int i = 0; i < 4; i++) {
                int r = i * 16 + r8;
                apf[i] = *(const float4*)&A[(size_t)(m0 + r) * K + kc + 32 + 4 * k4];
                bpf[i] = *(const float4*)&W[(size_t)(n0 + r) * K + kc + 32 + 4 * k4];
            }
        }

#pragma unroll
        for (int kk = 0; kk < 32; kk++) {
            u64 a2[4], bb[4];
#pragma unroll
            for (int p = 0; p < 4; p++) a2[p] = *(const u64*)&As[buf][kk][8 * ty + 2 * p];
#pragma unroll
            for (int j = 0; j < 4; j++) { float b = Bs[buf][kk][tx + 16 * j]; bb[j] = pk2(b, b); }
#pragma unroll
            for (int p = 0; p < 4; p++)
#pragma unroll
                for (int j = 0; j < 4; j++) fma2(acc2[p][j], a2[p], bb[j]);
        }
        __syncthreads();
    }

#pragma unroll
    for (int p = 0; p < 4; p++) {
#pragma unroll
        for (int j = 0; j < 4; j++) {
            int n = n0 + tx + 16 * j;
            float v0, v1;
            upk2(acc2[p][j], v0, v1);
            float bv = bias[n];
            int m = m0 + 8 * ty + 2 * p;
            C[(size_t)m * N + n]       = v0 + bv;
            C[(size_t)(m + 1) * N + n] = v1 + bv;
        }
    }
}

// ==================== fused post-attention block kernel (32-row stripe, split-k) ====
// 256 threads, 8 warps in 2 groups. Group wg computes 16-k chunks (c2+wg); private
// accumulators reduced through the dead A0 region once per GEMM. Warp tyl (0..3)
// owns rows 8tyl..8tyl+7 in BOTH groups; epilogues on group 0.
// smem (floats): A0[128][34] (later reduction scratch), X1[128][34], HS[256][34],
//                WS[2][16][132]
#define SM_A0 0
#define SM_X1 4352
#define SM_HS 8704
#define SM_WS 17408
#define WSBUF 2112
#define SM_FLOATS (SM_WS + 2 * WSBUF)   // 21632 floats = 86528 B

// LDG a pair of 16-k chunks (kA -> wpf[0..1], kB -> wpf[2..3])
#define LDG2(SRC, KA, KB, KW)                                                           \
    {                                                                                   \
        _Pragma("unroll")                                                               \
        for (int i = 0; i < 2; i++) {                                                   \
            int idx = i * 256 + tid;                                                    \
            wpf[i]     = *(const float4*)&(SRC)[(size_t)(idx >> 2) * (KW) + (KA) + 4 * (idx & 3)]; \
            wpf[i + 2] = *(const float4*)&(SRC)[(size_t)(idx >> 2) * (KW) + (KB) + 4 * (idx & 3)]; \
        }                                                                               \
    }

// STS both chunks: wpf[0..1] -> buf0, wpf[2..3] -> buf1
#define STS2()                                                                          \
    {                                                                                   \
        _Pragma("unroll")                                                               \
        for (int i = 0; i < 2; i++) {                                                   \
            int idx = i * 256 + tid;                                                    \
            int n = idx >> 2, kq = idx & 3;                                             \
            const float* va = (const float*)&wpf[i];                                    \
            const float* vb = (const float*)&wpf[i + 2];                                \
            _Pragma("unroll")                                                           \
            for (int c = 0; c < 4; c++) {                                               \
                sm[SM_WS + (4 * kq + c) * 132 + n]         = va[c];                     \
                sm[SM_WS + WSBUF + (4 * kq + c) * 132 + n] = vb[c];                     \
            }                                                                           \
        }                                                                               \
    }

// group-wise compute of chunk (c2+wg) from buf wg, A region ABASE (pitch 34)
#define GEMM_CHUNK2(ACCV, ABASE)                                                        \
    {                                                                                   \
        const int kcg = (c2 + wg) * 16;                                                 \
        const float* wsb = &sm[SM_WS + wg * WSBUF];                                     \
        u64 a2c[4], bbc[4];                                                             \
        _Pragma("unroll")                                                               \
        for (int p = 0; p < 4; p++)                                                     \
            a2c[p] = *(const u64*)&sm[(ABASE) + kcg * 34 + 8 * tyl + 2 * p];            \
        _Pragma("unroll")                                                               \
        for (int j = 0; j < 4; j++) { float b = wsb[tx + 32 * j]; bbc[j] = pk2(b, b); } \
        _Pragma("unroll")                                                               \
        for (int kk = 0; kk < 16; kk++) {                                               \
            int kn = (kk + 1) & 15;                                                     \
            u64 a2n[4], bbn[4];                                                         \
            _Pragma("unroll")                                                           \
            for (int p = 0; p < 4; p++)                                                 \
                a2n[p] = *(const u64*)&sm[(ABASE) + (kcg + kn) * 34 + 8 * tyl + 2 * p]; \
            _Pragma("unroll")                                                           \
            for (int j = 0; j < 4; j++) { float b = wsb[kn * 132 + tx + 32 * j]; bbn[j] = pk2(b, b); } \
            _Pragma("unroll")                                                           \
            for (int p = 0; p < 4; p++)                                                 \
                _Pragma("unroll")                                                       \
                for (int j = 0; j < 4; j++) fma2(ACCV[p][j], a2c[p], bbc[j]);           \
            _Pragma("unroll")                                                           \
            for (int p = 0; p < 4; p++) a2c[p] = a2n[p];                                \
            _Pragma("unroll")                                                           \
            for (int j = 0; j < 4; j++) bbc[j] = bbn[j];                                \
        }                                                                               \
    }

// cross-group reduction via A0 scratch (dead after GEMM1 compute)
#define REDUCE2(ACCV)                                                                   \
    {                                                                                   \
        u64* red = (u64*)(sm + SM_A0);                                                  \
        if (wg == 1) {                                                                  \
            _Pragma("unroll")                                                           \
            for (int p = 0; p < 4; p++)                                                 \
                _Pragma("unroll")                                                       \
                for (int j = 0; j < 4; j++)                                             \
                    red[(p * 4 + j) * 128 + tidl] = ACCV[p][j];                         \
        }                                                                               \
        __syncthreads();                                                                \
        if (wg == 0) {                                                                  \
            _Pragma("unroll")                                                           \
            for (int p = 0; p < 4; p++)                                                 \
                _Pragma("unroll")                                                       \
                for (int j = 0; j < 4; j++)                                             \
                    ACCV[p][j] = add2(ACCV[p][j], red[(p * 4 + j) * 128 + tidl]);       \
        }                                                                               \
    }

__global__ void __launch_bounds__(256) block_kernel(
    const float* __restrict__ ctx,
    const float* __restrict__ Wo, const float* __restrict__ bo,
    const float* __restrict__ ln1g, const float* __restrict__ ln1b,
    const float* __restrict__ W1, const float* __restrict__ b1,
    const float* __restrict__ W2, const float* __restrict__ b2,
    const float* __restrict__ ln2g, const float* __restrict__ ln2b)
{
    extern __shared__ float sm[];
    const int m0 = blockIdx.x * 32;
    const int tid = threadIdx.x;
    const int tx = tid & 31;
    const int ty = tid >> 5;        // warp 0..7
    const int wg = ty >> 2;         // warp-group 0/1
    const int tyl = ty & 3;         // row-warp within group: rows 8tyl..8tyl+7
    const int tidl = tid & 127;

    float4 wpf[4];

    // ---- prologue: LDG Wo chunks 0,1 + stage ctx k-major into A0[k][m] ----
    LDG2(Wo, 0, 16, Dm);
    {
        int rA = tid >> 3, k8 = tid & 7;   // row 0..31, 16-k group
        const float* rp = &ctx[(size_t)(m0 + rA) * Dm + 16 * k8];
#pragma unroll
        for (int c = 0; c < 4; c++) {
            float4 f = *(const float4*)(rp + 4 * c);
            int kb = 16 * k8 + 4 * c;
            sm[SM_A0 + (kb + 0) * 34 + rA] = f.x;
            sm[SM_A0 + (kb + 1) * 34 + rA] = f.y;
            sm[SM_A0 + (kb + 2) * 34 + rA] = f.z;
            sm[SM_A0 + (kb + 3) * 34 + rA] = f.w;
        }
    }
    STS2();
    __syncthreads();

    // ================= GEMM1: ctx @ Wo^T (K=128 -> 8 chunks) =================
    u64 acc[4][4];
#pragma unroll
    for (int p = 0; p < 4; p++)
#pragma unroll
        for (int j = 0; j < 4; j++) acc[p][j] = 0ull;

    for (int c2 = 0; c2 < 8; c2 += 2) {
        const bool more = (c2 + 2 < 8);
        if (more) LDG2(Wo, (c2 + 2) * 16, (c2 + 3) * 16, Dm);
        GEMM_CHUNK2(acc, SM_A0);
        __syncthreads();
        if (more) { STS2(); __syncthreads(); }
    }
    REDUCE2(acc);

    // ---- epilogue 1 (group 0): + bo + residual(g_x), LN1 -> X1[k=n][m] ----
    if (wg == 0) {
#pragma unroll
        for (int p = 0; p < 4; p++) {
            int m = m0 + 8 * tyl + 2 * p;
            float v0[4], v1[4];
            float s0 = 0.f, s1 = 0.f, q0 = 0.f, q1 = 0.f;
#pragma unroll
            for (int j = 0; j < 4; j++) {
                int n = tx + 32 * j;
                float x0, x1;
                upk2(acc[p][j], x0, x1);
                float bv = bo[n];
                v0[j] = x0 + bv + g_x[(size_t)m * Dm + n];
                v1[j] = x1 + bv + g_x[(size_t)(m + 1) * Dm + n];
                s0 += v0[j]; s1 += v1[j];
                q0 = fmaf(v0[j], v0[j], q0); q1 = fmaf(v1[j], v1[j], q1);
            }
            s0 = warp_sum(s0); s1 = warp_sum(s1);
            q0 = warp_sum(q0); q1 = warp_sum(q1);
            float mu0 = s0 * (1.f / Dm), mu1 = s1 * (1.f / Dm);
            float var0 = fmaf(-mu0, mu0, q0 * (1.f / Dm));
            float var1 = fmaf(-mu1, mu1, q1 * (1.f / Dm));
            float rs0 = rsqrtf(var0 + EPSf), rs1 = rsqrtf(var1 + EPSf);
            int ml = 8 * tyl + 2 * p;
#pragma unroll
            for (int j = 0; j < 4; j++) {
                int n = tx + 32 * j;
                float o0 = (v0[j] - mu0) * rs0 * ln1g[n] + ln1b[n];
                float o1 = (v1[j] - mu1) * rs1 * ln1g[n] + ln1b[n];
                *(u64*)&sm[SM_X1 + n * 34 + ml] = pk2(o0, o1);
            }
        }
    }

    // ================= GEMM2: x1 @ W1^T, relu (two 128-col halves, 8 chunks each) =====
#pragma unroll
    for (int h = 0; h < 2; h++) {
        const float* Wh = W1 + (size_t)(128 * h) * Dm;
        u64 acch[4][4];
#pragma unroll
        for (int p = 0; p < 4; p++)
#pragma unroll
            for (int j = 0; j < 4; j++) acch[p][j] = 0ull;

        LDG2(Wh, 0, 16, Dm);
        __syncthreads();   // X1 / HS(h-1) visible; prior WS reads + reduction reads done
        STS2();
        __syncthreads();

        for (int c2 = 0; c2 < 8; c2 += 2) {
            const bool more = (c2 + 2 < 8);
            if (more) LDG2(Wh, (c2 + 2) * 16, (c2 + 3) * 16, Dm);
            GEMM_CHUNK2(acch, SM_X1);
            __syncthreads();
            if (more) { STS2(); __syncthreads(); }
        }
        REDUCE2(acch);

        // epilogue (group 0): + b1, relu -> HS[k=n][m]
        if (wg == 0) {
            int ml = 8 * tyl;
#pragma unroll
            for (int p = 0; p < 4; p++) {
#pragma unroll
                for (int j = 0; j < 4; j++) {
                    int n = 128 * h + tx + 32 * j;
                    float h0, h1;
                    upk2(acch[p][j], h0, h1);
                    float bv = b1[n];
                    h0 = fmaxf(h0 + bv, 0.f);
                    h1 = fmaxf(h1 + bv, 0.f);
                    *(u64*)&sm[SM_HS + n * 34 + ml + 2 * p] = pk2(h0, h1);
                }
            }
        }
    }

    // ================= GEMM3: h @ W2^T (K=256 -> 16 chunks) =================
#pragma unroll
    for (int p = 0; p < 4; p++)
#pragma unroll
        for (int j = 0; j < 4; j++) acc[p][j] = 0ull;

    LDG2(W2, 0, 16, FFn);
    __syncthreads();   // HS visible; GEMM2 reads done
    STS2();
    __syncthreads();

    for (int c2 = 0; c2 < 16; c2 += 2) {
        const bool more = (c2 + 2 < 16);
        if (more) LDG2(W2, (c2 + 2) * 16, (c2 + 3) * 16, FFn);
        GEMM_CHUNK2(acc, SM_HS);
        __syncthreads();
        if (more) { STS2(); __syncthreads(); }
    }
    REDUCE2(acc);

    // ---- epilogue 3 (group 0): + b2 + x1 residual (X1 smem), LN2 -> g_x ----
    if (wg == 0) {
#pragma unroll
        for (int p = 0; p < 4; p++) {
            int m = m0 + 8 * tyl + 2 * p;
            int ml = 8 * tyl + 2 * p;
            float v0[4], v1[4];
            float s0 = 0.f, s1 = 0.f, q0 = 0.f, q1 = 0.f;
#pragma unroll
            for (int j = 0; j < 4; j++) {
                int n = tx + 32 * j;
                float x0, x1, r0, r1;
                upk2(acc[p][j], x0, x1);
                upk2(*(const u64*)&sm[SM_X1 + n * 34 + ml], r0, r1);
                float bv = b2[n];
                v0[j] = x0 + bv + r0;
                v1[j] = x1 + bv + r1;
                s0 += v0[j]; s1 += v1[j];
                q0 = fmaf(v0[j], v0[j], q0); q1 = fmaf(v1[j], v1[j], q1);
            }
            s0 = warp_sum(s0); s1 = warp_sum(s1);
            q0 = warp_sum(q0); q1 = warp_sum(q1);
            float mu0 = s0 * (1.f / Dm), mu1 = s1 * (1.f / Dm);
            float var0 = fmaf(-mu0, mu0, q0 * (1.f / Dm));
            float var1 = fmaf(-mu1, mu1, q1 * (1.f / Dm));
            float rs0 = rsqrtf(var0 + EPSf), rs1 = rsqrtf(var1 + EPSf);
#pragma unroll
            for (int j = 0; j < 4; j++) {
                int n = tx + 32 * j;
                g_x[(size_t)m * Dm + n]       = (v0[j] - mu0) * rs0 * ln2g[n] + ln2b[n];
                g_x[(size_t)(m + 1) * Dm + n] = (v1[j] - mu1) * rs1 * ln2g[n] + ln2b[n];
            }
        }
    }
}

// ---------------- local-window attention (warp-union broadcast + K prefetch) ---------
__global__ void __launch_bounds__(QB) attn_kernel() {
    __shared__ __align__(16) float Ks[NKMAX][16];
    __shared__ __align__(16) float Vs[NKMAX][16];
    const int q0 = blockIdx.x * QB;
    const int h = blockIdx.y, b = blockIdx.z;
    const int t = threadIdx.x;
    const int klo = max(0, q0 - LWn);
    const int khi = min(Sn - 1, q0 + QB - 1 + LWn);
    const int nk  = khi - klo + 1;   // <= 384
    const float* base = g_qkv + (size_t)b * Sn * (3 * Dm);

    {
        const int rq = t >> 2, cq = t & 3;
        for (int r0 = rq; r0 < nk; r0 += 32) {
            const float* rowp = base + (size_t)(klo + r0) * (3 * Dm) + h * HD + 4 * cq;
            *(float4*)&Ks[r0][4 * cq] = *(const float4*)(rowp + Dm);
            *(float4*)&Vs[r0][4 * cq] = *(const float4*)(rowp + 2 * Dm);
        }
    }

    const int q = q0 + t;
    u64 q2[8];
    {
        const float4* qp = (const float4*)(base + (size_t)q * (3 * Dm) + h * HD);
        const float sc = 0.25f * 1.44269504089f;   // fold 1/sqrt(16) * log2(e)
#pragma unroll
        for (int j = 0; j < 4; j++) {
            float4 f = qp[j];
            q2[2 * j]     = pk2(sc * f.x, sc * f.y);
            q2[2 * j + 1] = pk2(sc * f.z, sc * f.w);
        }
    }
    __syncthreads();

    const int wq0 = q0 + (t & ~31);
    const int wjlo = max(0, wq0 - LWn) - klo;
    const int wjhi = min(Sn - 1, wq0 + 31 + LWn) - klo;
    const int jlo = max(0, q - LWn) - klo;
    const unsigned jspan = (unsigned)(min(Sn - 1, q + LWn) - klo - jlo);

    float l = 0.f;
    u64 acc2[8];
#pragma unroll
    for (int d = 0; d < 8; d++) acc2[d] = 0ull;

    const ulonglong2* kr0 = (const ulonglong2*)Ks[wjlo];
    ulonglong2 kc0 = kr0[0], kc1 = kr0[1], kc2 = kr0[2], kc3 = kr0[3];

#pragma unroll 2
    for (int j = wjlo; j <= wjhi; j++) {
        int jn = (j < wjhi) ? j + 1 : j;
        const ulonglong2* krn = (const ulonglong2*)Ks[jn];
        ulonglong2 kn0 = krn[0], kn1 = krn[1], kn2 = krn[2], kn3 = krn[3];

        u64 dp0 = 0ull, dp1 = 0ull;
        fma2(dp0, q2[0], kc0.x); fma2(dp1, q2[1], kc0.y);
        fma2(dp0, q2[2], kc1.x); fma2(dp1, q2[3], kc1.y);
        fma2(dp0, q2[4], kc2.x); fma2(dp1, q2[5], kc2.y);
        fma2(dp0, q2[6], kc3.x); fma2(dp1, q2[7], kc3.y);
        float sx, sy;
        upk2(add2(dp0, dp1), sx, sy);
        float s = sx + sy;
        s = ((unsigned)(j - jlo) <= jspan) ? s : -10000.f;   // masked -> exp2 == 0
        float p = ex2f(s);
        l += p;
        u64 pp = pk2(p, p);
        const ulonglong2* vr = (const ulonglong2*)Vs[j];
        ulonglong2 v0 = vr[0], v1 = vr[1], v2 = vr[2], v3 = vr[3];
        fma2(acc2[0], pp, v0.x); fma2(acc2[1], pp, v0.y);
        fma2(acc2[2], pp, v1.x); fma2(acc2[3], pp, v1.y);
        fma2(acc2[4], pp, v2.x); fma2(acc2[5], pp, v2.y);
        fma2(acc2[6], pp, v3.x); fma2(acc2[7], pp, v3.y);

        kc0 = kn0; kc1 = kn1; kc2 = kn2; kc3 = kn3;
    }

    float inv = 1.f / l;
    float* cp = g_ctx + (size_t)(b * Sn + q) * Dm + h * HD;
#pragma unroll
    for (int d = 0; d < 8; d++) {
        float x, y;
        upk2(acc2[d], x, y);
        cp[2 * d] = x * inv; cp[2 * d + 1] = y * inv;
    }
}

// ---------------- final LN + linear head + softplus ----------------
__global__ void __launch_bounds__(128) final_kernel(
    const float* __restrict__ g, const float* __restrict__ bb,
    const float* __restrict__ Wout, const float* __restrict__ bout,
    float* __restrict__ out)
{
    const int row = blockIdx.x, d = threadIdx.x;
    float v = g_x[(size_t)row * Dm + d];
    __shared__ float r1[4], r2[4], r3[4];
    float s = warp_sum(v);
    if ((d & 31) == 0) r1[d >> 5] = s;
    __syncthreads();
    float mean = (r1[0] + r1[1] + r1[2] + r1[3]) * (1.f / Dm);
    float dv = v - mean;
    float s2 = warp_sum(dv * dv);
    if ((d & 31) == 0) r2[d >> 5] = s2;
    __syncthreads();
    float var = (r2[0] + r2[1] + r2[2] + r2[3]) * (1.f / Dm);
    float xn = dv * rsqrtf(var + EPSf) * g[d] + bb[d];
    float p = warp_sum(xn * Wout[d]);
    if ((d & 31) == 0) r3[d >> 5] = p;
    __syncthreads();
    if (d == 0) {
        float z = r3[0] + r3[1] + r3[2] + r3[3] + bout[0];
        out[row] = (z > 15.f) ? z : log1pf(expf(z));
    }
}

// ---------------- launch ----------------
extern "C" void kernel_launch(void* const* d_in, const int* in_sizes, int n_in,
                              void* d_out, int out_size)
{
    const int*   tok  = (const int*)d_in[0];
    const float* emb  = (const float*)d_in[1];
    const float* Wqkv = (const float*)d_in[2];
    const float* bqkv = (const float*)d_in[3];
    const float* Wo   = (const float*)d_in[4];
    const float* bo   = (const float*)d_in[5];
    const float* ln1g = (const float*)d_in[6];
    const float* ln1b = (const float*)d_in[7];
    const float* ln2g = (const float*)d_in[8];
    const float* ln2b = (const float*)d_in[9];
    const float* W1   = (const float*)d_in[10];
    const float* b1   = (const float*)d_in[11];
    const float* W2   = (const float*)d_in[12];
    const float* b2   = (const float*)d_in[13];
    const float* lnfg = (const float*)d_in[14];
    const float* lnfb = (const float*)d_in[15];
    const float* Wout = (const float*)d_in[16];
    const float* bout = (const float*)d_in[17];
    float* out = (float*)d_out;

    float *px, *pqkv, *pctx;
    cudaGetSymbolAddress((void**)&px,   g_x);
    cudaGetSymbolAddress((void**)&pqkv, g_qkv);
    cudaGetSymbolAddress((void**)&pctx, g_ctx);

    const int smem_bytes = SM_FLOATS * 4;   // 86528
    cudaFuncSetAttribute(block_kernel, cudaFuncAttributeMaxDynamicSharedMemorySize, smem_bytes);

    embed_kernel<<<(ROWS * Dm) / 256, 256>>>(tok, emb);

    for (int l = 0; l < Lnum; l++) {
        const float* Wqkv_l = Wqkv + (size_t)l * 3 * Dm * Dm;
        const float* bqkv_l = bqkv + (size_t)l * 3 * Dm;

        gemm64x64<<<dim3(6, ROWS / 64), 128>>>(px, Wqkv_l, bqkv_l, pqkv, 3 * Dm, Dm);
        attn_kernel<<<dim3(Sn / QB, Hn, Bn), QB>>>();
        block_kernel<<<ROWS / 32, 256, smem_bytes>>>(
            pctx,
            Wo + (size_t)l * Dm * Dm,  bo + (size_t)l * Dm,
            ln1g + (size_t)l * Dm,     ln1b + (size_t)l * Dm,
            W1 + (size_t)l * FFn * Dm, b1 + (size_t)l * FFn,
            W2 + (size_t)l * Dm * FFn, b2 + (size_t)l * Dm,
            ln2g + (size_t)l * Dm,     ln2b + (size_t)l * Dm);
    }

    final_kernel<<<ROWS, 128>>>(lnfg, lnfb, Wout, bout, out);
}

// round 14
// speedup vs baseline: 1.0365x; 1.0365x over previous
#include <cuda_runtime.h>
#include <math.h>

#define Bn   8
#define Sn   1024
#define Dm   128
#define Hn   8
#define HD   16
#define FFn  256
#define Lnum 4
#define LWn  128
#define EPSf 1e-5f
#define ROWS (Bn * Sn)   // 8192
#define QB   128               // attention queries per block
#define NKMAX (QB + 2 * LWn)   // 384

typedef unsigned long long u64;

// ---------------- scratch (static device memory; no runtime allocs) ----------------
__device__ float g_x[ROWS * Dm];
__device__ float g_qkv[ROWS * 3 * Dm];
__device__ float g_ctx[ROWS * Dm];

__device__ __forceinline__ float warp_sum(float v) {
#pragma unroll
    for (int o = 16; o > 0; o >>= 1) v += __shfl_xor_sync(0xffffffffu, v, o);
    return v;
}

// ---- packed f32x2 helpers (Blackwell dual-FP32) ----
__device__ __forceinline__ u64 pk2(float x, float y) {
    u64 r;
    asm("mov.b64 %0, {%1, %2};" : "=l"(r) : "f"(x), "f"(y));
    return r;
}
__device__ __forceinline__ void upk2(u64 v, float& x, float& y) {
    asm("mov.b64 {%0, %1}, %2;" : "=f"(x), "=f"(y) : "l"(v));
}
__device__ __forceinline__ void fma2(u64& d, u64 a, u64 b) {
    asm("fma.rn.f32x2 %0, %1, %2, %0;" : "+l"(d) : "l"(a), "l"(b));
}
__device__ __forceinline__ u64 add2(u64 a, u64 b) {
    u64 r;
    asm("add.rn.f32x2 %0, %1, %2;" : "=l"(r) : "l"(a), "l"(b));
    return r;
}
__device__ __forceinline__ float ex2f(float x) {
    float r;
    asm("ex2.approx.f32 %0, %1;" : "=f"(r) : "f"(x));
    return r;
}

// ---------------- embedding + sinusoidal positions ----------------
__global__ void embed_kernel(const int* __restrict__ tok, const float* __restrict__ emb) {
    int idx = blockIdx.x * blockDim.x + threadIdx.x;
    int d  = idx & (Dm - 1);
    int bs = idx >> 7;
    int s  = bs & (Sn - 1);
    int v  = tok[bs];
    int i2 = d & ~1;
    float div = expf(-(float)i2 * (logf(10000.0f) / (float)Dm));
    float arg = (float)s * div;
    float pe  = (d & 1) ? cosf(arg) : sinf(arg);
    g_x[idx] = emb[v * Dm + d] + pe;
}

// ---------------- GEMM 64x64: C = A @ W^T + bias (QKV projection) ----------------
// kk register pipelining: load kk+1's operands while FMA'ing kk.
__global__ void __launch_bounds__(128) gemm64x64(
    const float* __restrict__ A, const float* __restrict__ W,
    const float* __restrict__ bias, float* __restrict__ C, int N, int K)
{
    __shared__ float As[2][32][66];
    __shared__ float Bs[2][32][66];

    const int m0 = blockIdx.y * 64, n0 = blockIdx.x * 64;
    const int tid = threadIdx.x;
    const int tx = tid & 15;
    const int ty = tid >> 4;
    const int r8 = tid >> 3;
    const int k4 = tid & 7;

    u64 acc2[4][4];
#pragma unroll
    for (int p = 0; p < 4; p++)
#pragma unroll
        for (int j = 0; j < 4; j++) acc2[p][j] = 0ull;

    float4 apf[4], bpf[4];
#pragma unroll
    for (int i = 0; i < 4; i++) {
        int r = i * 16 + r8;
        apf[i] = *(const float4*)&A[(size_t)(m0 + r) * K + 4 * k4];
        bpf[i] = *(const float4*)&W[(size_t)(n0 + r) * K + 4 * k4];
    }

    int buf = 0;
    for (int kc = 0; kc < K; kc += 32, buf ^= 1) {
#pragma unroll
        for (int i = 0; i < 4; i++) {
            int r = i * 16 + r8;
#pragma unroll
            for (int c = 0; c < 4; c++) {
                As[buf][4 * k4 + c][r] = ((const float*)&apf[i])[c];
                Bs[buf][4 * k4 + c][r] = ((const float*)&bpf[i])[c];
            }
        }
        __syncthreads();

        if (kc + 32 < K) {
#pragma unroll
            for (int i = 0; i < 4; i++) {
                int r = i * 16 + r8;
                apf[i] = *(const float4*)&A[(size_t)(m0 + r) * K + kc + 32 + 4 * k4];
                bpf[i] = *(const float4*)&W[(size_t)(n0 + r) * K + kc + 32 + 4 * k4];
            }
        }

        u64 a2c[4], bbc[4];
#pragma unroll
        for (int p = 0; p < 4; p++) a2c[p] = *(const u64*)&As[buf][0][8 * ty + 2 * p];
#pragma unroll
        for (int j = 0; j < 4; j++) { float b = Bs[buf][0][tx + 16 * j]; bbc[j] = pk2(b, b); }

#pragma unroll
        for (int kk = 0; kk < 32; kk++) {
            int kn = (kk + 1) & 31;
            u64 a2n[4], bbn[4];
#pragma unroll
            for (int p = 0; p < 4; p++) a2n[p] = *(const u64*)&As[buf][kn][8 * ty + 2 * p];
#pragma unroll
            for (int j = 0; j < 4; j++) { float b = Bs[buf][kn][tx + 16 * j]; bbn[j] = pk2(b, b); }
#pragma unroll
            for (int p = 0; p < 4; p++)
#pragma unroll
                for (int j = 0; j < 4; j++) fma2(acc2[p][j], a2c[p], bbc[j]);
#pragma unroll
            for (int p = 0; p < 4; p++) a2c[p] = a2n[p];
#pragma unroll
            for (int j = 0; j < 4; j++) bbc[j] = bbn[j];
        }
        __syncthreads();
    }

#pragma unroll
    for (int p = 0; p < 4; p++) {
#pragma unroll
        for (int j = 0; j < 4; j++) {
            int n = n0 + tx + 16 * j;
            float v0, v1;
            upk2(acc2[p][j], v0, v1);
            float bv = bias[n];
            int m = m0 + 8 * ty + 2 * p;
            C[(size_t)m * N + n]       = v0 + bv;
            C[(size_t)(m + 1) * N + n] = v1 + bv;
        }
    }
}

// ==================== fused post-attention block kernel (32-row stripe) ====================
// 128 threads, 4 warps; warp ty owns rows 8ty..8ty+7 (4 m-pairs). Microtile 8x4 via f32x2.
// smem (floats): A0[128][34], X1[128][34], HS[256][34], WS[2][16][132]
#define SM_A0 0
#define SM_X1 4352
#define SM_HS 8704
#define SM_WS 17408
#define WSBUF 2112
#define SM_FLOATS (SM_WS + 2 * WSBUF)   // 21632 floats = 86528 B

__global__ void __launch_bounds__(128) block_kernel(
    const float* __restrict__ ctx,
    const float* __restrict__ Wo, const float* __restrict__ bo,
    const float* __restrict__ ln1g, const float* __restrict__ ln1b,
    const float* __restrict__ W1, const float* __restrict__ b1,
    const float* __restrict__ W2, const float* __restrict__ b2,
    const float* __restrict__ ln2g, const float* __restrict__ ln2b)
{
    extern __shared__ float sm[];
    const int m0 = blockIdx.x * 32;
    const int tid = threadIdx.x;
    const int tx = tid & 31;
    const int ty = tid >> 5;        // warp 0..3: rows 8ty..8ty+7

    // ---- LDG Wo chunk0 + stage ctx k-major into A0[k][m] ----
    float4 wpf[4];
#pragma unroll
    for (int i = 0; i < 4; i++) {
        int idx = i * 128 + tid;
        wpf[i] = *(const float4*)&Wo[(size_t)(idx >> 2) * Dm + 4 * (idx & 3)];
    }
    {
        int rA = tid >> 2, kq = tid & 3;   // row 0..31, 32-k group
        const float* rp = &ctx[(size_t)(m0 + rA) * Dm + 32 * kq];
#pragma unroll
        for (int c = 0; c < 8; c++) {
            float4 f = *(const float4*)(rp + 4 * c);
            int kb = 32 * kq + 4 * c;
            sm[SM_A0 + (kb + 0) * 34 + rA] = f.x;
            sm[SM_A0 + (kb + 1) * 34 + rA] = f.y;
            sm[SM_A0 + (kb + 2) * 34 + rA] = f.z;
            sm[SM_A0 + (kb + 3) * 34 + rA] = f.w;
        }
    }
    // STS Wo chunk0: WS[k][n], plain
    {
#pragma unroll
        for (int i = 0; i < 4; i++) {
            int idx = i * 128 + tid;
            int n = idx >> 2, kq = idx & 3;
            const float* v = (const float*)&wpf[i];
#pragma unroll
            for (int c = 0; c < 4; c++)
                sm[SM_WS + (4 * kq + c) * 132 + n] = v[c];
        }
    }
    __syncthreads();

    // ================= GEMM1: ctx @ Wo^T (K=128, N=128) =================
    u64 acc[4][4];
#pragma unroll
    for (int p = 0; p < 4; p++)
#pragma unroll
        for (int j = 0; j < 4; j++) acc[p][j] = 0ull;

    int buf = 0;
    for (int kc = 0; kc < 128; kc += 16, buf ^= 1) {
        const bool more = (kc + 16 < 128);
        if (more) {
#pragma unroll
            for (int i = 0; i < 4; i++) {
                int idx = i * 128 + tid;
                wpf[i] = *(const float4*)&Wo[(size_t)(idx >> 2) * Dm + kc + 16 + 4 * (idx & 3)];
            }
        }
        const float* wsb = &sm[SM_WS + buf * WSBUF];
        u64 a2c[4], bbc[4];
#pragma unroll
        for (int p = 0; p < 4; p++) a2c[p] = *(const u64*)&sm[SM_A0 + kc * 34 + 8 * ty + 2 * p];
#pragma unroll
        for (int j = 0; j < 4; j++) { float b = wsb[tx + 32 * j]; bbc[j] = pk2(b, b); }
#pragma unroll
        for (int kk = 0; kk < 16; kk++) {
            int kn = (kk + 1) & 15;
            u64 a2n[4], bbn[4];
#pragma unroll
            for (int p = 0; p < 4; p++)
                a2n[p] = *(const u64*)&sm[SM_A0 + (kc + kn) * 34 + 8 * ty + 2 * p];
#pragma unroll
            for (int j = 0; j < 4; j++) { float b = wsb[kn * 132 + tx + 32 * j]; bbn[j] = pk2(b, b); }
#pragma unroll
            for (int p = 0; p < 4; p++)
#pragma unroll
                for (int j = 0; j < 4; j++) fma2(acc[p][j], a2c[p], bbc[j]);
#pragma unroll
            for (int p = 0; p < 4; p++) a2c[p] = a2n[p];
#pragma unroll
            for (int j = 0; j < 4; j++) bbc[j] = bbn[j];
        }
        if (more) {
#pragma unroll
            for (int i = 0; i < 4; i++) {
                int idx = i * 128 + tid;
                int n = idx >> 2, kq = idx & 3;
                float* wsn = &sm[SM_WS + (buf ^ 1) * WSBUF];
                const float* v = (const float*)&wpf[i];
#pragma unroll
                for (int c = 0; c < 4; c++)
                    wsn[(4 * kq + c) * 132 + n] = v[c];
            }
        }
        __syncthreads();
    }

    // ---- epilogue 1: + bo + residual(g_x), LN1 -> X1[k=n][m] ----
#pragma unroll
    for (int p = 0; p < 4; p++) {
        int m = m0 + 8 * ty + 2 * p;
        float v0[4], v1[4];
        float s0 = 0.f, s1 = 0.f, q0 = 0.f, q1 = 0.f;
#pragma unroll
        for (int j = 0; j < 4; j++) {
            int n = tx + 32 * j;
            float x0, x1;
            upk2(acc[p][j], x0, x1);
            float bv = bo[n];
            v0[j] = x0 + bv + g_x[(size_t)m * Dm + n];
            v1[j] = x1 + bv + g_x[(size_t)(m + 1) * Dm + n];
            s0 += v0[j]; s1 += v1[j];
            q0 = fmaf(v0[j], v0[j], q0); q1 = fmaf(v1[j], v1[j], q1);
        }
        s0 = warp_sum(s0); s1 = warp_sum(s1);
        q0 = warp_sum(q0); q1 = warp_sum(q1);
        float mu0 = s0 * (1.f / Dm), mu1 = s1 * (1.f / Dm);
        float var0 = fmaf(-mu0, mu0, q0 * (1.f / Dm));
        float var1 = fmaf(-mu1, mu1, q1 * (1.f / Dm));
        float rs0 = rsqrtf(var0 + EPSf), rs1 = rsqrtf(var1 + EPSf);
        int ml = 8 * ty + 2 * p;
#pragma unroll
        for (int j = 0; j < 4; j++) {
            int n = tx + 32 * j;
            float o0 = (v0[j] - mu0) * rs0 * ln1g[n] + ln1b[n];
            float o1 = (v1[j] - mu1) * rs1 * ln1g[n] + ln1b[n];
            *(u64*)&sm[SM_X1 + n * 34 + ml] = pk2(o0, o1);
        }
    }

    // ================= GEMM2: x1 @ W1^T, relu (K=128, N=256 in two 128 halves) ========
#pragma unroll
    for (int h = 0; h < 2; h++) {
        const float* Wh = W1 + (size_t)(128 * h) * Dm;
        u64 acch[4][4];
#pragma unroll
        for (int p = 0; p < 4; p++)
#pragma unroll
            for (int j = 0; j < 4; j++) acch[p][j] = 0ull;

#pragma unroll
        for (int i = 0; i < 4; i++) {
            int idx = i * 128 + tid;
            wpf[i] = *(const float4*)&Wh[(size_t)(idx >> 2) * Dm + 4 * (idx & 3)];
        }
        __syncthreads();   // X1 (h=0) / HS h-1 epilogue (h=1) visible; prior WS reads done
        {
#pragma unroll
            for (int i = 0; i < 4; i++) {
                int idx = i * 128 + tid;
                int n = idx >> 2, kq = idx & 3;
                const float* v = (const float*)&wpf[i];
#pragma unroll
                for (int c = 0; c < 4; c++)
                    sm[SM_WS + (4 * kq + c) * 132 + n] = v[c];
            }
        }
        __syncthreads();

        buf = 0;
        for (int kc = 0; kc < 128; kc += 16, buf ^= 1) {
            const bool more = (kc + 16 < 128);
            if (more) {
#pragma unroll
                for (int i = 0; i < 4; i++) {
                    int idx = i * 128 + tid;
                    wpf[i] = *(const float4*)&Wh[(size_t)(idx >> 2) * Dm + kc + 16 + 4 * (idx & 3)];
                }
            }
            const float* wsb = &sm[SM_WS + buf * WSBUF];
            u64 a2c[4], bbc[4];
#pragma unroll
            for (int p = 0; p < 4; p++) a2c[p] = *(const u64*)&sm[SM_X1 + kc * 34 + 8 * ty + 2 * p];
#pragma unroll
            for (int j = 0; j < 4; j++) { float b = wsb[tx + 32 * j]; bbc[j] = pk2(b, b); }
#pragma unroll
            for (int kk = 0; kk < 16; kk++) {
                int kn = (kk + 1) & 15;
                u64 a2n[4], bbn[4];
#pragma unroll
                for (int p = 0; p < 4; p++)
                    a2n[p] = *(const u64*)&sm[SM_X1 + (kc + kn) * 34 + 8 * ty + 2 * p];
#pragma unroll
                for (int j = 0; j < 4; j++) { float b = wsb[kn * 132 + tx + 32 * j]; bbn[j] = pk2(b, b); }
#pragma unroll
                for (int p = 0; p < 4; p++)
#pragma unroll
                    for (int j = 0; j < 4; j++) fma2(acch[p][j], a2c[p], bbc[j]);
#pragma unroll
                for (int p = 0; p < 4; p++) a2c[p] = a2n[p];
#pragma unroll
                for (int j = 0; j < 4; j++) bbc[j] = bbn[j];
            }
            if (more) {
#pragma unroll
                for (int i = 0; i < 4; i++) {
                    int idx = i * 128 + tid;
                    int n = idx >> 2, kq = idx & 3;
                    float* wsn = &sm[SM_WS + (buf ^ 1) * WSBUF];
                    const float* v = (const float*)&wpf[i];
#pragma unroll
                    for (int c = 0; c < 4; c++)
                        wsn[(4 * kq + c) * 132 + n] = v[c];
                }
            }
            __syncthreads();
        }

        // epilogue: + b1, relu -> HS[k=n][m]
        int ml = 8 * ty;
#pragma unroll
        for (int p = 0; p < 4; p++) {
#pragma unroll
            for (int j = 0; j < 4; j++) {
                int n = 128 * h + tx + 32 * j;
                float h0, h1;
                upk2(acch[p][j], h0, h1);
                float bv = b1[n];
                h0 = fmaxf(h0 + bv, 0.f);
                h1 = fmaxf(h1 + bv, 0.f);
                *(u64*)&sm[SM_HS + n * 34 + ml + 2 * p] = pk2(h0, h1);
            }
        }
    }

    // ================= GEMM3: h @ W2^T (K=256, N=128) =================
#pragma unroll
    for (int p = 0; p < 4; p++)
#pragma unroll
        for (int j = 0; j < 4; j++) acc[p][j] = 0ull;

#pragma unroll
    for (int i = 0; i < 4; i++) {
        int idx = i * 128 + tid;
        wpf[i] = *(const float4*)&W2[(size_t)(idx >> 2) * FFn + 4 * (idx & 3)];
    }
    __syncthreads();   // HS visible; GEMM2 WS reads done
    {
#pragma unroll
        for (int i = 0; i < 4; i++) {
            int idx = i * 128 + tid;
            int n = idx >> 2, kq = idx & 3;
            const float* v = (const float*)&wpf[i];
#pragma unroll
            for (int c = 0; c < 4; c++)
                sm[SM_WS + (4 * kq + c) * 132 + n] = v[c];
        }
    }
    __syncthreads();

    buf = 0;
    for (int kc = 0; kc < 256; kc += 16, buf ^= 1) {
        const bool more = (kc + 16 < 256);
        if (more) {
#pragma unroll
            for (int i = 0; i < 4; i++) {
                int idx = i * 128 + tid;
                wpf[i] = *(const float4*)&W2[(size_t)(idx >> 2) * FFn + kc + 16 + 4 * (idx & 3)];
            }
        }
        const float* wsb = &sm[SM_WS + buf * WSBUF];
        u64 a2c[4], bbc[4];
#pragma unroll
        for (int p = 0; p < 4; p++) a2c[p] = *(const u64*)&sm[SM_HS + kc * 34 + 8 * ty + 2 * p];
#pragma unroll
        for (int j = 0; j < 4; j++) { float b = wsb[tx + 32 * j]; bbc[j] = pk2(b, b); }
#pragma unroll
        for (int kk = 0; kk < 16; kk++) {
            int kn = (kk + 1) & 15;
            u64 a2n[4], bbn[4];
#pragma unroll
            for (int p = 0; p < 4; p++)
                a2n[p] = *(const u64*)&sm[SM_HS + (kc + kn) * 34 + 8 * ty + 2 * p];
#pragma unroll
            for (int j = 0; j < 4; j++) { float b = wsb[kn * 132 + tx + 32 * j]; bbn[j] = pk2(b, b); }
#pragma unroll
            for (int p = 0; p < 4; p++)
#pragma unroll
                for (int j = 0; j < 4; j++) fma2(acc[p][j], a2c[p], bbc[j]);
#pragma unroll
            for (int p = 0; p < 4; p++) a2c[p] = a2n[p];
#pragma unroll
            for (int j = 0; j < 4; j++) bbc[j] = bbn[j];
        }
        if (more) {
#pragma unroll
            for (int i = 0; i < 4; i++) {
                int idx = i * 128 + tid;
                int n = idx >> 2, kq = idx & 3;
                float* wsn = &sm[SM_WS + (buf ^ 1) * WSBUF];
                const float* v = (const float*)&wpf[i];
#pragma unroll
                for (int c = 0; c < 4; c++)
                    wsn[(4 * kq + c) * 132 + n] = v[c];
            }
        }
        __syncthreads();
    }

    // ---- epilogue 3: + b2 + x1 residual (X1 smem), LN2 -> g_x ----
#pragma unroll
    for (int p = 0; p < 4; p++) {
        int m = m0 + 8 * ty + 2 * p;
        int ml = 8 * ty + 2 * p;
        float v0[4], v1[4];
        float s0 = 0.f, s1 = 0.f, q0 = 0.f, q1 = 0.f;
#pragma unroll
        for (int j = 0; j < 4; j++) {
            int n = tx + 32 * j;
            float x0, x1, r0, r1;
            upk2(acc[p][j], x0, x1);
            upk2(*(const u64*)&sm[SM_X1 + n * 34 + ml], r0, r1);
            float bv = b2[n];
            v0[j] = x0 + bv + r0;
            v1[j] = x1 + bv + r1;
            s0 += v0[j]; s1 += v1[j];
            q0 = fmaf(v0[j], v0[j], q0); q1 = fmaf(v1[j], v1[j], q1);
        }
        s0 = warp_sum(s0); s1 = warp_sum(s1);
        q0 = warp_sum(q0); q1 = warp_sum(q1);
        float mu0 = s0 * (1.f / Dm), mu1 = s1 * (1.f / Dm);
        float var0 = fmaf(-mu0, mu0, q0 * (1.f / Dm));
        float var1 = fmaf(-mu1, mu1, q1 * (1.f / Dm));
        float rs0 = rsqrtf(var0 + EPSf), rs1 = rsqrtf(var1 + EPSf);
#pragma unroll
        for (int j = 0; j < 4; j++) {
            int n = tx + 32 * j;
            g_x[(size_t)m * Dm + n]       = (v0[j] - mu0) * rs0 * ln2g[n] + ln2b[n];
            g_x[(size_t)(m + 1) * Dm + n] = (v1[j] - mu1) * rs1 * ln2g[n] + ln2b[n];
        }
    }
}

// ---------------- local-window attention (warp-union broadcast + K prefetch) ---------
__global__ void __launch_bounds__(QB) attn_kernel() {
    __shared__ __align__(16) float Ks[NKMAX][16];
    __shared__ __align__(16) float Vs[NKMAX][16];
    const int q0 = blockIdx.x * QB;
    const int h = blockIdx.y, b = blockIdx.z;
    const int t = threadIdx.x;
    const int klo = max(0, q0 - LWn);
    const int khi = min(Sn - 1, q0 + QB - 1 + LWn);
    const int nk  = khi - klo + 1;   // <= 384
    const float* base = g_qkv + (size_t)b * Sn * (3 * Dm);

    {
        const int rq = t >> 2, cq = t & 3;
        for (int r0 = rq; r0 < nk; r0 += 32) {
            const float* rowp = base + (size_t)(klo + r0) * (3 * Dm) + h * HD + 4 * cq;
            *(float4*)&Ks[r0][4 * cq] = *(const float4*)(rowp + Dm);
            *(float4*)&Vs[r0][4 * cq] = *(const float4*)(rowp + 2 * Dm);
        }
    }

    const int q = q0 + t;
    u64 q2[8];
    {
        const float4* qp = (const float4*)(base + (size_t)q * (3 * Dm) + h * HD);
        const float sc = 0.25f * 1.44269504089f;   // fold 1/sqrt(16) * log2(e)
#pragma unroll
        for (int j = 0; j < 4; j++) {
            float4 f = qp[j];
            q2[2 * j]     = pk2(sc * f.x, sc * f.y);
            q2[2 * j + 1] = pk2(sc * f.z, sc * f.w);
        }
    }
    __syncthreads();

    const int wq0 = q0 + (t & ~31);
    const int wjlo = max(0, wq0 - LWn) - klo;
    const int wjhi = min(Sn - 1, wq0 + 31 + LWn) - klo;
    const int jlo = max(0, q - LWn) - klo;
    const unsigned jspan = (unsigned)(min(Sn - 1, q + LWn) - klo - jlo);

    float l = 0.f;
    u64 acc2[8];
#pragma unroll
    for (int d = 0; d < 8; d++) acc2[d] = 0ull;

    const ulonglong2* kr0 = (const ulonglong2*)Ks[wjlo];
    ulonglong2 kc0 = kr0[0], kc1 = kr0[1], kc2 = kr0[2], kc3 = kr0[3];

#pragma unroll 2
    for (int j = wjlo; j <= wjhi; j++) {
        int jn = (j < wjhi) ? j + 1 : j;
        const ulonglong2* krn = (const ulonglong2*)Ks[jn];
        ulonglong2 kn0 = krn[0], kn1 = krn[1], kn2 = krn[2], kn3 = krn[3];

        u64 dp0 = 0ull, dp1 = 0ull;
        fma2(dp0, q2[0], kc0.x); fma2(dp1, q2[1], kc0.y);
        fma2(dp0, q2[2], kc1.x); fma2(dp1, q2[3], kc1.y);
        fma2(dp0, q2[4], kc2.x); fma2(dp1, q2[5], kc2.y);
        fma2(dp0, q2[6], kc3.x); fma2(dp1, q2[7], kc3.y);
        float sx, sy;
        upk2(add2(dp0, dp1), sx, sy);
        float s = sx + sy;
        s = ((unsigned)(j - jlo) <= jspan) ? s : -10000.f;   // masked -> exp2 == 0
        float p = ex2f(s);
        l += p;
        u64 pp = pk2(p, p);
        const ulonglong2* vr = (const ulonglong2*)Vs[j];
        ulonglong2 v0 = vr[0], v1 = vr[1], v2 = vr[2], v3 = vr[3];
        fma2(acc2[0], pp, v0.x); fma2(acc2[1], pp, v0.y);
        fma2(acc2[2], pp, v1.x); fma2(acc2[3], pp, v1.y);
        fma2(acc2[4], pp, v2.x); fma2(acc2[5], pp, v2.y);
        fma2(acc2[6], pp, v3.x); fma2(acc2[7], pp, v3.y);

        kc0 = kn0; kc1 = kn1; kc2 = kn2; kc3 = kn3;
    }

    float inv = 1.f / l;
    float* cp = g_ctx + (size_t)(b * Sn + q) * Dm + h * HD;
#pragma unroll
    for (int d = 0; d < 8; d++) {
        float x, y;
        upk2(acc2[d], x, y);
        cp[2 * d] = x * inv; cp[2 * d + 1] = y * inv;
    }
}

// ---------------- final LN + linear head + softplus (warp per row, no barriers) -------
__global__ void __launch_bounds__(256) final_kernel(
    const float* __restrict__ g, const float* __restrict__ bb,
    const float* __restrict__ Wout, const float* __restrict__ bout,
    float* __restrict__ out)
{
    const int warp = threadIdx.x >> 5;
    const int lane = threadIdx.x & 31;
    const int row = blockIdx.x * 8 + warp;

    float4 xv = *(const float4*)&g_x[(size_t)row * Dm + 4 * lane];
    float s = warp_sum((xv.x + xv.y) + (xv.z + xv.w));
    float mean = s * (1.f / Dm);
    float d0 = xv.x - mean, d1 = xv.y - mean, d2 = xv.z - mean, d3 = xv.w - mean;
    float s2 = warp_sum(fmaf(d0, d0, fmaf(d1, d1, fmaf(d2, d2, d3 * d3))));
    float rs = rsqrtf(s2 * (1.f / Dm) + EPSf);

    float4 gv = *(const float4*)&g[4 * lane];
    float4 bv = *(const float4*)&bb[4 * lane];
    float4 wv = *(const float4*)&Wout[4 * lane];
    float xn0 = d0 * rs * gv.x + bv.x;
    float xn1 = d1 * rs * gv.y + bv.y;
    float xn2 = d2 * rs * gv.z + bv.z;
    float xn3 = d3 * rs * gv.w + bv.w;
    float p = warp_sum(fmaf(xn0, wv.x, fmaf(xn1, wv.y, fmaf(xn2, wv.z, xn3 * wv.w))));
    if (lane == 0) {
        float z = p + bout[0];
        out[row] = (z > 15.f) ? z : log1pf(expf(z));
    }
}

// ---------------- launch ----------------
extern "C" void kernel_launch(void* const* d_in, const int* in_sizes, int n_in,
                              void* d_out, int out_size)
{
    const int*   tok  = (const int*)d_in[0];
    const float* emb  = (const float*)d_in[1];
    const float* Wqkv = (const float*)d_in[2];
    const float* bqkv = (const float*)d_in[3];
    const float* Wo   = (const float*)d_in[4];
    const float* bo   = (const float*)d_in[5];
    const float* ln1g = (const float*)d_in[6];
    const float* ln1b = (const float*)d_in[7];
    const float* ln2g = (const float*)d_in[8];
    const float* ln2b = (const float*)d_in[9];
    const float* W1   = (const float*)d_in[10];
    const float* b1   = (const float*)d_in[11];
    const float* W2   = (const float*)d_in[12];
    const float* b2   = (const float*)d_in[13];
    const float* lnfg = (const float*)d_in[14];
    const float* lnfb = (const float*)d_in[15];
    const float* Wout = (const float*)d_in[16];
    const float* bout = (const float*)d_in[17];
    float* out = (float*)d_out;

    float *px, *pqkv, *pctx;
    cudaGetSymbolAddress((void**)&px,   g_x);
    cudaGetSymbolAddress((void**)&pqkv, g_qkv);
    cudaGetSymbolAddress((void**)&pctx, g_ctx);

    const int smem_bytes = SM_FLOATS * 4;   // 86528
    cudaFuncSetAttribute(block_kernel, cudaFuncAttributeMaxDynamicSharedMemorySize, smem_bytes);

    embed_kernel<<<(ROWS * Dm) / 256, 256>>>(tok, emb);

    for (int l = 0; l < Lnum; l++) {
        const float* Wqkv_l = Wqkv + (size_t)l * 3 * Dm * Dm;
        const float* bqkv_l = bqkv + (size_t)l * 3 * Dm;

        gemm64x64<<<dim3(6, ROWS / 64), 128>>>(px, Wqkv_l, bqkv_l, pqkv, 3 * Dm, Dm);
        attn_kernel<<<dim3(Sn / QB, Hn, Bn), QB>>>();
        block_kernel<<<ROWS / 32, 128, smem_bytes>>>(
            pctx,
            Wo + (size_t)l * Dm * Dm,  bo + (size_t)l * Dm,
            ln1g + (size_t)l * Dm,     ln1b + (size_t)l * Dm,
            W1 + (size_t)l * FFn * Dm, b1 + (size_t)l * FFn,
            W2 + (size_t)l * Dm * FFn, b2 + (size_t)l * Dm,
            ln2g + (size_t)l * Dm,     ln2b + (size_t)l * Dm);
    }

    final_kernel<<<ROWS / 8, 256>>>(lnfg, lnfb, Wout, bout, out);
}